// round 1
// baseline (speedup 1.0000x reference)
#include <cuda_runtime.h>
#include <stdint.h>

// Problem constants (fixed by setup_inputs)
#define BB 512        // batch rows
#define NN 100000     // reference points
#define DD 10         // logit dim
#define CC 3072       // x feature dim
#define KNN 50
#define RBITS 10
#define NBINS 1024
#define USHIFT 22     // 32 - RBITS
#define RROWS 8       // rows per CTA tile
#define RGRP (BB / RROWS)   // 64
#define JCH 8         // j-chunks per row-group
#define CAP 8192      // candidate buffer per row
#define TPB 256

// Scratch (static device globals — allocation-free)
__device__ float              g_L[BB * DD];
__device__ float              g_scale[BB];
__device__ float              g_Xp[NN * 12];          // x0..x9, xsq, yf  (48B rows, float4-aligned)
__device__ unsigned           g_hist[BB * NBINS];     // 2 MB
__device__ int                g_pivot[BB];
__device__ int                g_below[BB];
__device__ float              g_votes[BB];
__device__ int                g_ccount[BB];
__device__ unsigned long long g_cand[(size_t)BB * CAP]; // 32 MB

// Order-preserving float -> uint map
__device__ __forceinline__ unsigned mono(float f) {
    unsigned u = __float_as_uint(f);
    return u ^ ((unsigned)((int)u >> 31) | 0x80000000u);
}

// Key = xsq - 2 * dot(L, x). Explicit fmaf chain => bitwise identical across passes.
__device__ __forceinline__ float keyval(const float* L, const float* xv, float xsq) {
    float acc = 0.f;
#pragma unroll
    for (int c = 0; c < DD; c++) acc = fmaf(L[c], xv[c], acc);
    return fmaf(-2.f, acc, xsq);
}

// ---------------------------------------------------------------------------
// Kernel 0: zero scratch + pack X rows (x, xsq, yf) into 48B records
// ---------------------------------------------------------------------------
__global__ void k_prep(const float* __restrict__ X, const int* __restrict__ Y) {
    int i = blockIdx.x * TPB + threadIdx.x;
    if (i < BB * NBINS) g_hist[i] = 0u;
    if (i < BB) { g_votes[i] = 0.f; g_ccount[i] = 0; }
    if (i < NN) {
        float v[DD];
        float xsq = 0.f;
#pragma unroll
        for (int c = 0; c < DD; c++) { v[c] = X[i * DD + c]; xsq = fmaf(v[c], v[c], xsq); }
        float4* p = (float4*)&g_Xp[i * 12];
        p[0] = make_float4(v[0], v[1], v[2], v[3]);
        p[1] = make_float4(v[4], v[5], v[6], v[7]);
        p[2] = make_float4(v[8], v[9], xsq, (float)(2 * Y[i] - 1));
    }
}

// ---------------------------------------------------------------------------
// Kernel 1: logits = x @ W + b ; also 2*max|logit| per row; write out[:, 0:10]
// ---------------------------------------------------------------------------
__global__ void k_logits(const float* __restrict__ x, const float* __restrict__ W,
                         const float* __restrict__ bias, float* __restrict__ out) {
    int row = blockIdx.x, tid = threadIdx.x;
    float acc[DD];
#pragma unroll
    for (int c = 0; c < DD; c++) acc[c] = 0.f;
    const float* xr = x + (size_t)row * CC;
    for (int k = tid; k < CC; k += TPB) {
        float xv = xr[k];
        const float* wr = W + (size_t)k * DD;
#pragma unroll
        for (int c = 0; c < DD; c++) acc[c] = fmaf(xv, wr[c], acc[c]);
    }
    __shared__ float s[DD * TPB];
#pragma unroll
    for (int c = 0; c < DD; c++) s[c * TPB + tid] = acc[c];
    __syncthreads();
    for (int st = TPB / 2; st > 0; st >>= 1) {
        if (tid < st) {
#pragma unroll
            for (int c = 0; c < DD; c++) s[c * TPB + tid] += s[c * TPB + tid + st];
        }
        __syncthreads();
    }
    if (tid == 0) {
        float mx = 0.f;
#pragma unroll
        for (int c = 0; c < DD; c++) {
            float l = s[c * TPB] + bias[c];
            g_L[row * DD + c] = l;
            out[row * 11 + c] = l;
            mx = fmaxf(mx, fabsf(l));
        }
        g_scale[row] = 2.f * mx;
    }
}

// ---------------------------------------------------------------------------
// Kernel 2: per-row 10-bit radix histogram of keys (warp-aggregated atomics)
// ---------------------------------------------------------------------------
__global__ void __launch_bounds__(TPB, 2) k_hist() {
    __shared__ unsigned sh[RROWS * NBINS];  // 32 KB
    int tid = threadIdx.x, lane = tid & 31;
    int row0 = blockIdx.x * RROWS;
    for (int i = tid; i < RROWS * NBINS; i += TPB) sh[i] = 0u;
    float L[RROWS][DD];
#pragma unroll
    for (int r = 0; r < RROWS; r++)
#pragma unroll
        for (int c = 0; c < DD; c++) L[r][c] = g_L[(row0 + r) * DD + c];
    __syncthreads();

    const int chunk = (NN + JCH - 1) / JCH;
    int jbeg = blockIdx.y * chunk;
    int jend = min(NN, jbeg + chunk);
    int steps = (jend - jbeg + TPB - 1) / TPB;
    for (int s = 0; s < steps; s++) {
        int j = jbeg + s * TPB + tid;
        bool valid = (j < jend);
        float xv[DD];
        float xsq = 0.f;
        if (valid) {
            const float4* p = (const float4*)&g_Xp[(size_t)j * 12];
            float4 a = p[0], b = p[1], c4 = p[2];
            xv[0] = a.x; xv[1] = a.y; xv[2] = a.z; xv[3] = a.w;
            xv[4] = b.x; xv[5] = b.y; xv[6] = b.z; xv[7] = b.w;
            xv[8] = c4.x; xv[9] = c4.y; xsq = c4.z;
        }
#pragma unroll
        for (int r = 0; r < RROWS; r++) {
            int bin = -1;
            if (valid) bin = (int)(mono(keyval(L[r], xv, xsq)) >> USHIFT);
            unsigned peers = __match_any_sync(0xFFFFFFFFu, bin);
            int leader = __ffs(peers) - 1;
            if (valid && lane == leader)
                atomicAdd(&sh[r * NBINS + bin], (unsigned)__popc(peers));
        }
    }
    __syncthreads();
    for (int i = tid; i < RROWS * NBINS; i += TPB) {
        unsigned v = sh[i];
        if (v) atomicAdd(&g_hist[(row0 + (i >> RBITS)) * NBINS + (i & (NBINS - 1))], v);
    }
}

// ---------------------------------------------------------------------------
// Kernel 3: per-row scan of histogram -> pivot bin + exact count strictly below
// ---------------------------------------------------------------------------
__global__ void k_pivot() {
    int row = blockIdx.x, tid = threadIdx.x;
    const unsigned* h = &g_hist[row * NBINS];
    unsigned c0 = h[tid * 4 + 0], c1 = h[tid * 4 + 1], c2 = h[tid * 4 + 2], c3 = h[tid * 4 + 3];
    unsigned mysum = c0 + c1 + c2 + c3;
    __shared__ unsigned s[TPB];
    s[tid] = mysum;
    __syncthreads();
    for (int off = 1; off < TPB; off <<= 1) {
        unsigned v = (tid >= off) ? s[tid - off] : 0u;
        __syncthreads();
        s[tid] += v;
        __syncthreads();
    }
    unsigned incl = s[tid];
    unsigned excl = incl - mysum;
    if (excl < KNN && incl >= KNN) {
        unsigned run = excl;
        unsigned cs[4] = {c0, c1, c2, c3};
#pragma unroll
        for (int k = 0; k < 4; k++) {
            if (run + cs[k] >= KNN) { g_pivot[row] = tid * 4 + k; g_below[row] = (int)run; break; }
            run += cs[k];
        }
    }
}

// ---------------------------------------------------------------------------
// Kernel 4: classify pass — votes for bins < pivot, candidates for bin == pivot
// ---------------------------------------------------------------------------
__global__ void __launch_bounds__(TPB, 2) k_classify() {
    int tid = threadIdx.x;
    int row0 = blockIdx.x * RROWS;
    float L[RROWS][DD];
    int pv[RROWS];
    float vs[RROWS];
#pragma unroll
    for (int r = 0; r < RROWS; r++) {
        pv[r] = g_pivot[row0 + r];
        vs[r] = 0.f;
#pragma unroll
        for (int c = 0; c < DD; c++) L[r][c] = g_L[(row0 + r) * DD + c];
    }
    const int chunk = (NN + JCH - 1) / JCH;
    int jbeg = blockIdx.y * chunk;
    int jend = min(NN, jbeg + chunk);
    for (int j = jbeg + tid; j < jend; j += TPB) {
        const float4* p = (const float4*)&g_Xp[(size_t)j * 12];
        float4 a = p[0], b = p[1], c4 = p[2];
        float xv[DD] = {a.x, a.y, a.z, a.w, b.x, b.y, b.z, b.w, c4.x, c4.y};
        float xsq = c4.z, yf = c4.w;
#pragma unroll
        for (int r = 0; r < RROWS; r++) {
            unsigned u = mono(keyval(L[r], xv, xsq));
            int bin = (int)(u >> USHIFT);
            if (bin < pv[r]) {
                vs[r] += yf;
            } else if (bin == pv[r]) {
                int slot = atomicAdd(&g_ccount[row0 + r], 1);
                if (slot < CAP)
                    g_cand[(size_t)(row0 + r) * CAP + slot] =
                        ((unsigned long long)u << 32) | (unsigned)j;
            }
        }
    }
    // exact vote reduction (sums of +-1 are exact integers in fp32)
#pragma unroll
    for (int r = 0; r < RROWS; r++) {
        float v = vs[r];
#pragma unroll
        for (int off = 16; off > 0; off >>= 1) v += __shfl_down_sync(0xFFFFFFFFu, v, off);
        if ((tid & 31) == 0 && v != 0.f) atomicAdd(&g_votes[row0 + r], v);
    }
}

// ---------------------------------------------------------------------------
// Kernel 5: per-row select (50 - below) smallest candidates by (key, index),
//           finish votes, write adversarial logit
// ---------------------------------------------------------------------------
__global__ void k_final(float* __restrict__ out) {
    int row = blockIdx.x, tid = threadIdx.x;
    int c = min(g_ccount[row], CAP);
    int need = KNN - g_below[row];
    const unsigned long long* cd = &g_cand[(size_t)row * CAP];
    float local = 0.f;
    for (int i = tid; i < c; i += TPB) {
        unsigned long long v = cd[i];
        int rank = 0;
        for (int k = 0; k < c; k++) rank += (cd[k] < v);
        if (rank < need) {
            int j = (int)(v & 0xFFFFFFFFu);
            local += g_Xp[(size_t)j * 12 + 11];  // yf
        }
    }
    __shared__ float sv[TPB];
    sv[tid] = local;
    __syncthreads();
    for (int st = TPB / 2; st > 0; st >>= 1) {
        if (tid < st) sv[tid] += sv[tid + st];
        __syncthreads();
    }
    if (tid == 0) {
        float v = g_votes[row] + sv[0];  // + BIAS (= 0)
        float sgn = (v > 0.f) ? 1.f : ((v < 0.f) ? -1.f : 0.f);
        out[row * 11 + 10] = sgn * g_scale[row];
    }
}

// ---------------------------------------------------------------------------
extern "C" void kernel_launch(void* const* d_in, const int* in_sizes, int n_in,
                              void* d_out, int out_size) {
    const float* x    = (const float*)d_in[0];
    const float* W    = (const float*)d_in[1];
    const float* bias = (const float*)d_in[2];
    const float* X    = (const float*)d_in[3];
    const int*   Y    = (const int*)d_in[4];
    float* out = (float*)d_out;

    k_prep<<<(BB * NBINS + TPB - 1) / TPB, TPB>>>(X, Y);
    k_logits<<<BB, TPB>>>(x, W, bias, out);
    k_hist<<<dim3(RGRP, JCH), TPB>>>();
    k_pivot<<<BB, TPB>>>();
    k_classify<<<dim3(RGRP, JCH), TPB>>>();
    k_final<<<BB, TPB>>>(out);
}

// round 3
// speedup vs baseline: 1.5917x; 1.5917x over previous
#include <cuda_runtime.h>
#include <stdint.h>

// Problem constants (fixed by setup_inputs)
#define BB 512        // batch rows
#define NN 100000     // reference points
#define DD 10         // logit dim
#define CC 3072       // x feature dim
#define KNN 50
#define RROWS 8       // rows per CTA tile in main pass
#define RGRP (BB / RROWS)   // 64
#define JCH 8         // j-chunks per row-group
#define CAP 8192      // candidate buffer per row
#define TPB 256
#define SSAMP 4096    // sample size (first SSAMP points)
#define MSEL 48       // threshold = MSEL-th smallest sample key
#define TIECAP 512

// Scratch (static device globals — allocation-free)
__device__ float              g_L[BB * DD];
__device__ float              g_scale[BB];
__device__ float              g_T[BB];
__device__ float              g_Xp[NN * 12];          // x0..x9, xsq, yf (48B, float4-aligned)
__device__ unsigned           g_skey[BB * SSAMP];     // 8 MB sample keys (mono)
__device__ int                g_ccount[BB];
__device__ unsigned long long g_cand[(size_t)BB * CAP]; // 32 MB

// Order-preserving float -> uint map and inverse
__device__ __forceinline__ unsigned mono(float f) {
    unsigned u = __float_as_uint(f);
    return u ^ ((unsigned)((int)u >> 31) | 0x80000000u);
}
__device__ __forceinline__ float unmono(unsigned v) {
    unsigned u = (v & 0x80000000u) ? (v ^ 0x80000000u) : ~v;
    return __uint_as_float(u);
}

// Scalar key: xsq - 2*dot(L,x), fixed fmaf order (bitwise-stable across kernels)
__device__ __forceinline__ float keyval(const float* L, const float* xv, float xsq) {
    float acc = 0.f;
#pragma unroll
    for (int c = 0; c < DD; c++) acc = fmaf(L[c], xv[c], acc);
    return fmaf(-2.f, acc, xsq);
}

// Packed f32x2 helpers (Blackwell)
__device__ __forceinline__ unsigned long long pk(float lo, float hi) {
    unsigned long long r;
    asm("mov.b64 %0, {%1, %2};" : "=l"(r) : "f"(lo), "f"(hi));
    return r;
}
__device__ __forceinline__ void fma2(unsigned long long& d, unsigned long long a,
                                     unsigned long long b) {
    asm("fma.rn.f32x2 %0, %1, %2, %0;" : "+l"(d) : "l"(a), "l"(b));
}
__device__ __forceinline__ unsigned long long fma2g(unsigned long long a, unsigned long long b,
                                                    unsigned long long c) {
    unsigned long long d;
    asm("fma.rn.f32x2 %0, %1, %2, %3;" : "=l"(d) : "l"(a), "l"(b), "l"(c));
    return d;
}
__device__ __forceinline__ void upk(float& lo, float& hi, unsigned long long v) {
    asm("mov.b64 {%0, %1}, %2;" : "=f"(lo), "=f"(hi) : "l"(v));
}

// ---------------------------------------------------------------------------
// Kernel 0: zero counters + pack X rows (x, xsq, yf) into 48B records
// ---------------------------------------------------------------------------
__global__ void k_prep(const float* __restrict__ X, const int* __restrict__ Y) {
    int i = blockIdx.x * TPB + threadIdx.x;
    if (i < BB) g_ccount[i] = 0;
    if (i < NN) {
        float v[DD];
        float xsq = 0.f;
#pragma unroll
        for (int c = 0; c < DD; c++) { v[c] = X[i * DD + c]; xsq = fmaf(v[c], v[c], xsq); }
        float4* p = (float4*)&g_Xp[i * 12];
        p[0] = make_float4(v[0], v[1], v[2], v[3]);
        p[1] = make_float4(v[4], v[5], v[6], v[7]);
        p[2] = make_float4(v[8], v[9], xsq, (float)(2 * Y[i] - 1));
    }
}

// ---------------------------------------------------------------------------
// Kernel 1: logits = x @ W + b (warp per row); 2*max|logit|; out[:,0:10]
// ---------------------------------------------------------------------------
__global__ void k_logits(const float* __restrict__ x, const float* __restrict__ W,
                         const float* __restrict__ bias, float* __restrict__ out) {
    int warp = threadIdx.x >> 5, lane = threadIdx.x & 31;
    int row = blockIdx.x * 8 + warp;
    const float* xr = x + (size_t)row * CC;
    float acc[DD];
#pragma unroll
    for (int c = 0; c < DD; c++) acc[c] = 0.f;
    for (int k = lane; k < CC; k += 32) {
        float xv = xr[k];
        const float* wr = W + (size_t)k * DD;
#pragma unroll
        for (int c = 0; c < DD; c++) acc[c] = fmaf(xv, wr[c], acc[c]);
    }
#pragma unroll
    for (int c = 0; c < DD; c++)
#pragma unroll
        for (int off = 16; off > 0; off >>= 1)
            acc[c] += __shfl_down_sync(0xFFFFFFFFu, acc[c], off);
    if (lane == 0) {
        float mx = 0.f;
#pragma unroll
        for (int c = 0; c < DD; c++) {
            float l = acc[c] + bias[c];
            g_L[row * DD + c] = l;
            out[row * 11 + c] = l;
            mx = fmaxf(mx, fabsf(l));
        }
        g_scale[row] = 2.f * mx;
    }
}

// ---------------------------------------------------------------------------
// Kernel 2: sample keys — first SSAMP points, 8 rows per CTA
// ---------------------------------------------------------------------------
__global__ void k_skey() {
    int tid = threadIdx.x;
    int row0 = blockIdx.x * RROWS;
    float L[RROWS][DD];
#pragma unroll
    for (int r = 0; r < RROWS; r++)
#pragma unroll
        for (int c = 0; c < DD; c++) L[r][c] = g_L[(row0 + r) * DD + c];
    for (int s = tid; s < SSAMP; s += TPB) {
        const float4* p = (const float4*)&g_Xp[(size_t)s * 12];
        float4 a = p[0], b = p[1], c4 = p[2];
        float xv[DD] = {a.x, a.y, a.z, a.w, b.x, b.y, b.z, b.w, c4.x, c4.y};
#pragma unroll
        for (int r = 0; r < RROWS; r++)
            g_skey[(size_t)(row0 + r) * SSAMP + s] = mono(keyval(L[r], xv, c4.z));
    }
}

// ---------------------------------------------------------------------------
// Kernel 3: per-row radix-select MSEL-th smallest sample key -> float threshold
// ---------------------------------------------------------------------------
__global__ void k_thresh() {
    int row = blockIdx.x, tid = threadIdx.x;
    const unsigned* sk = &g_skey[(size_t)row * SSAMP];
    __shared__ unsigned hist[256];
    __shared__ unsigned s_sel, s_run;
    unsigned prefix = 0;
    int remaining = MSEL;
    for (int pass = 0; pass < 4; pass++) {
        int shift = 24 - 8 * pass;
        unsigned maskhi = pass ? (0xFFFFFFFFu << (32 - 8 * pass)) : 0u;
        if (tid < 256) hist[tid] = 0u;
        __syncthreads();
        for (int i = tid; i < SSAMP; i += TPB) {
            unsigned u = sk[i];
            if ((u & maskhi) == prefix) atomicAdd(&hist[(u >> shift) & 255], 1u);
        }
        __syncthreads();
        if (tid == 0) {
            unsigned run = 0, b = 0;
            for (; b < 256; b++) {
                if (run + hist[b] >= (unsigned)remaining) break;
                run += hist[b];
            }
            s_sel = b; s_run = run;
        }
        __syncthreads();
        remaining -= (int)s_run;
        prefix |= s_sel << shift;
        __syncthreads();
    }
    if (tid == 0) g_T[row] = unmono(prefix);
}

// ---------------------------------------------------------------------------
// Kernel 4: main pass — packed f32x2 keys for 8 rows/CTA, append candidates
// ---------------------------------------------------------------------------
__global__ void __launch_bounds__(TPB, 2) k_main() {
    int tid = threadIdx.x;
    int row0 = blockIdx.x * RROWS;
    unsigned long long Lp[RROWS / 2][DD];
    float Tf[RROWS];
#pragma unroll
    for (int p = 0; p < RROWS / 2; p++)
#pragma unroll
        for (int c = 0; c < DD; c++)
            Lp[p][c] = pk(g_L[(row0 + 2 * p) * DD + c], g_L[(row0 + 2 * p + 1) * DD + c]);
#pragma unroll
    for (int r = 0; r < RROWS; r++) Tf[r] = g_T[row0 + r];
    const unsigned long long M2 = pk(-2.f, -2.f);

    const int chunk = (NN + JCH - 1) / JCH;
    int jbeg = blockIdx.y * chunk;
    int jend = min(NN, jbeg + chunk);
    for (int j = jbeg + tid; j < jend; j += TPB) {
        const float4* p4 = (const float4*)&g_Xp[(size_t)j * 12];
        float4 a = p4[0], b = p4[1], c4 = p4[2];
        unsigned long long xx[DD];
        xx[0] = pk(a.x, a.x); xx[1] = pk(a.y, a.y); xx[2] = pk(a.z, a.z); xx[3] = pk(a.w, a.w);
        xx[4] = pk(b.x, b.x); xx[5] = pk(b.y, b.y); xx[6] = pk(b.z, b.z); xx[7] = pk(b.w, b.w);
        xx[8] = pk(c4.x, c4.x); xx[9] = pk(c4.y, c4.y);
        unsigned long long xs2 = pk(c4.z, c4.z);
#pragma unroll
        for (int p = 0; p < RROWS / 2; p++) {
            unsigned long long acc = 0ull;  // (0.0f, 0.0f)
#pragma unroll
            for (int c = 0; c < DD; c++) fma2(acc, Lp[p][c], xx[c]);
            unsigned long long kk = fma2g(M2, acc, xs2);
            float k0, k1;
            upk(k0, k1, kk);
            if (k0 <= Tf[2 * p]) {
                int row = row0 + 2 * p;
                int slot = atomicAdd(&g_ccount[row], 1);
                if (slot < CAP)
                    g_cand[(size_t)row * CAP + slot] =
                        ((unsigned long long)mono(k0) << 32) | (unsigned)j;
            }
            if (k1 <= Tf[2 * p + 1]) {
                int row = row0 + 2 * p + 1;
                int slot = atomicAdd(&g_ccount[row], 1);
                if (slot < CAP)
                    g_cand[(size_t)row * CAP + slot] =
                        ((unsigned long long)mono(k1) << 32) | (unsigned)j;
            }
        }
    }
}

// ---------------------------------------------------------------------------
// Kernel 5: correctness net — exact per-row bisection if candidates bad
//           (normally exits immediately; deterministic)
// ---------------------------------------------------------------------------
__global__ void k_fallback() {
    int row = blockIdx.x, tid = threadIdx.x;
    int c = g_ccount[row];
    if (c >= KNN && c <= CAP) return;
    float L[DD];
#pragma unroll
    for (int i = 0; i < DD; i++) L[i] = g_L[row * DD + i];
    __shared__ int scnt[TPB];
    unsigned lo = 0u, hi = 0xFFFFFFFFu;
    for (int it = 0; it < 32 && lo < hi; it++) {
        unsigned mid = lo + ((hi - lo) >> 1);
        int cnt = 0;
        for (int j = tid; j < NN; j += TPB) {
            const float4* p = (const float4*)&g_Xp[(size_t)j * 12];
            float4 a = p[0], b = p[1], c4 = p[2];
            float xv[DD] = {a.x, a.y, a.z, a.w, b.x, b.y, b.z, b.w, c4.x, c4.y};
            cnt += (mono(keyval(L, xv, c4.z)) <= mid);
        }
        scnt[tid] = cnt;
        __syncthreads();
        for (int st = TPB / 2; st > 0; st >>= 1) {
            if (tid < st) scnt[tid] += scnt[tid + st];
            __syncthreads();
        }
        int tot = scnt[0];
        __syncthreads();
        if (tot >= KNN) hi = mid; else lo = mid + 1;
    }
    if (tid == 0) g_ccount[row] = 0;
    __syncthreads();
    for (int j = tid; j < NN; j += TPB) {
        const float4* p = (const float4*)&g_Xp[(size_t)j * 12];
        float4 a = p[0], b = p[1], c4 = p[2];
        float xv[DD] = {a.x, a.y, a.z, a.w, b.x, b.y, b.z, b.w, c4.x, c4.y};
        unsigned u = mono(keyval(L, xv, c4.z));
        if (u <= lo) {
            int slot = atomicAdd(&g_ccount[row], 1);
            if (slot < CAP)
                g_cand[(size_t)row * CAP + slot] = ((unsigned long long)u << 32) | (unsigned)j;
        }
    }
}

// ---------------------------------------------------------------------------
// Kernel 6: per-row exact radix-select of 50th key among candidates,
//           tie-break by smallest index, sum votes, write adversarial logit
// ---------------------------------------------------------------------------
__global__ void k_final(float* __restrict__ out) {
    int row = blockIdx.x, tid = threadIdx.x;
    int c = min(g_ccount[row], CAP);
    const unsigned long long* cd = &g_cand[(size_t)row * CAP];
    __shared__ unsigned hist[256];
    __shared__ unsigned s_sel, s_run;
    unsigned prefix = 0;
    int remaining = KNN;
    for (int pass = 0; pass < 4; pass++) {
        int shift = 24 - 8 * pass;
        unsigned maskhi = pass ? (0xFFFFFFFFu << (32 - 8 * pass)) : 0u;
        if (tid < 256) hist[tid] = 0u;
        __syncthreads();
        for (int i = tid; i < c; i += TPB) {
            unsigned u = (unsigned)(cd[i] >> 32);
            if ((u & maskhi) == prefix) atomicAdd(&hist[(u >> shift) & 255], 1u);
        }
        __syncthreads();
        if (tid == 0) {
            unsigned run = 0, b = 0;
            for (; b < 256; b++) {
                if (run + hist[b] >= (unsigned)remaining) break;
                run += hist[b];
            }
            s_sel = b; s_run = run;
        }
        __syncthreads();
        remaining -= (int)s_run;
        prefix |= s_sel << shift;
        __syncthreads();
    }
    unsigned k50 = prefix;
    int t = remaining;  // take t smallest-index elements among key==k50 ties

    __shared__ int s_tn;
    __shared__ unsigned tiebuf[TIECAP];
    if (tid == 0) s_tn = 0;
    __syncthreads();
    float local = 0.f;
    for (int i = tid; i < c; i += TPB) {
        unsigned long long v = cd[i];
        unsigned u = (unsigned)(v >> 32);
        unsigned j = (unsigned)(v & 0xFFFFFFFFu);
        if (u < k50) {
            local += g_Xp[(size_t)j * 12 + 11];
        } else if (u == k50) {
            int p = atomicAdd(&s_tn, 1);
            if (p < TIECAP) tiebuf[p] = j;
        }
    }
    __syncthreads();
    int nt = min(s_tn, TIECAP);
    for (int i = tid; i < nt; i += TPB) {
        unsigned ji = tiebuf[i];
        int rank = 0;
        for (int k = 0; k < nt; k++) rank += (tiebuf[k] < ji);
        if (rank < t) local += g_Xp[(size_t)ji * 12 + 11];
    }
    __shared__ float sv[TPB];
    sv[tid] = local;
    __syncthreads();
    for (int st = TPB / 2; st > 0; st >>= 1) {
        if (tid < st) sv[tid] += sv[tid + st];
        __syncthreads();
    }
    if (tid == 0) {
        float v = sv[0];  // + BIAS (= 0)
        float sgn = (v > 0.f) ? 1.f : ((v < 0.f) ? -1.f : 0.f);
        out[row * 11 + 10] = sgn * g_scale[row];
    }
}

// ---------------------------------------------------------------------------
extern "C" void kernel_launch(void* const* d_in, const int* in_sizes, int n_in,
                              void* d_out, int out_size) {
    const float* x    = (const float*)d_in[0];
    const float* W    = (const float*)d_in[1];
    const float* bias = (const float*)d_in[2];
    const float* X    = (const float*)d_in[3];
    const int*   Y    = (const int*)d_in[4];
    float* out = (float*)d_out;

    k_prep<<<(NN + TPB - 1) / TPB, TPB>>>(X, Y);
    k_logits<<<BB / 8, TPB>>>(x, W, bias, out);
    k_skey<<<RGRP, TPB>>>();
    k_thresh<<<BB, TPB>>>();
    k_main<<<dim3(RGRP, JCH), TPB>>>();
    k_fallback<<<BB, TPB>>>();
    k_final<<<BB, TPB>>>(out);
}